// round 14
// baseline (speedup 1.0000x reference)
#include <cuda_runtime.h>
#include <cuda_fp16.h>
#include <cstdint>
#include <math_constants.h>

// ---------------------------------------------------------------------------
// Problem constants
// ---------------------------------------------------------------------------
#define B_  10
#define T_  100
#define A_  20
#define NIN 4096
#define NIMG 1024
#define NATT 512
#define NPHYS 256
#define BT  (B_*T_)            // 1000
#define NPAIR 190
#define MPAIR (BT*NPAIR)       // 190000

// Scratch (allocation-free rule: __device__ globals)
__device__ __align__(256) __half g_xh [(size_t)BT * A_ * NIN];   // fp16 x
__device__ __align__(256) __half g_wlh[(size_t)NATT * NIN];      // fp16 W_loc
__device__ __align__(256) __half g_wgh[(size_t)NIMG * NIN];      // fp16 W_glob
__device__ __align__(256) __half g_w3h[NPHYS * NPHYS];           // fp16 W_phys3
__device__ __align__(256) __half g_physh[(size_t)MPAIR * NPHYS]; // fp16 phys

// ---------------------------------------------------------------------------
// PTX helpers (sm_80-class ISA — tcgen05 rejected by this toolchain)
// ---------------------------------------------------------------------------
__device__ __forceinline__ uint32_t smem_u32(const void* p) {
    uint32_t a;
    asm("{ .reg .u64 t; cvta.to.shared.u64 t, %1; cvt.u32.u64 %0, t; }"
        : "=r"(a) : "l"(p));
    return a;
}

__device__ __forceinline__ void ldsm_x4(uint32_t* r, uint32_t addr) {
    asm volatile("ldmatrix.sync.aligned.m8n8.x4.shared.b16 {%0,%1,%2,%3}, [%4];"
                 : "=r"(r[0]), "=r"(r[1]), "=r"(r[2]), "=r"(r[3]) : "r"(addr));
}

__device__ __forceinline__ void mma_f16(float* d, const uint32_t* a,
                                        uint32_t b0, uint32_t b1) {
    asm volatile(
        "mma.sync.aligned.m16n8k16.row.col.f32.f16.f16.f32 "
        "{%0,%1,%2,%3}, {%4,%5,%6,%7}, {%8,%9}, {%0,%1,%2,%3};"
        : "+f"(d[0]), "+f"(d[1]), "+f"(d[2]), "+f"(d[3])
        : "r"(a[0]), "r"(a[1]), "r"(a[2]), "r"(a[3]), "r"(b0), "r"(b1));
}

__device__ __forceinline__ void cp_async16(uint32_t dst, const void* src, int sz) {
    asm volatile("cp.async.cg.shared.global [%0], [%1], 16, %2;"
                 :: "r"(dst), "l"(src), "r"(sz));
}

// ---------------------------------------------------------------------------
// fp32 -> fp16 convert (grid-stride, float4 -> 2x half2)
// ---------------------------------------------------------------------------
__global__ void cvt_f2h(const float* __restrict__ src, __half* __restrict__ dst,
                        int n4)
{
    const int stride = gridDim.x * blockDim.x;
    for (int i = blockIdx.x * blockDim.x + threadIdx.x; i < n4; i += stride) {
        const float4 v = ((const float4*)src)[i];
        ((__half2*)dst)[2 * i + 0] = __floats2half2_rn(v.x, v.y);
        ((__half2*)dst)[2 * i + 1] = __floats2half2_rn(v.z, v.w);
    }
}

__global__ void warm_kernel() {}

// ---------------------------------------------------------------------------
// fp16 GEMM: C[M,N] = gatherA[M,K] @ Bw[N,K]^T + bias (fp32 out)
//   mode 1: A row r at r*(20*4096)                    (glob: x[:,:,0,:])
//   mode 2: A row r at ((r/19)*20 + r%19 + 1)*4096    (loc: x[:,:,1:,:])
// CTA 128x128, 128 threads (4 warps x 64x64), BK=64, 3-stage, 2 CTA/SM.
// (round-7/11 configuration — best measured; no fragment double-buffer)
// ---------------------------------------------------------------------------
#define STG_A 0
#define STG_B 16384
#define STAGE_BYTES 32768
#define SM_GEMM (3 * STAGE_BYTES)   // 98304

struct GemmDesc {
    const __half* A; const __half* Bw; const float* bias; float* C;
    int M, N, K, mode;
};

__device__ __forceinline__ void gemm_core(const GemmDesc g, int idx, uint32_t sb)
{
    const __half* __restrict__ A  = g.A;
    const __half* __restrict__ Bw = g.Bw;
    const int M = g.M, N = g.N, K = g.K, mode = g.mode;

    const int nx   = N >> 7;
    const int row0 = (idx / nx) * 128;
    const int col0 = (idx % nx) * 128;

    const int tid  = threadIdx.x;
    const int wid  = tid >> 5;
    const int lane = tid & 31;
    const int wm = (wid & 1) * 64;
    const int wn = (wid >> 1) * 64;

    long aoff[8]; int avalid[8]; uint32_t dstA[8];
    long boff[8]; uint32_t dstB[8];
    #pragma unroll
    for (int j = 0; j < 8; j++) {
        const int e = tid + j * 128;
        const int r = e >> 3, kc = e & 7;
        const uint32_t sw = (uint32_t)(r * 128 + ((kc ^ (r & 7)) * 16));
        dstA[j] = sb + STG_A + sw;
        dstB[j] = sb + STG_B + sw;
        const int am = row0 + r;
        avalid[j] = (am < M) ? 16 : 0;
        const int amc = (am < M) ? am : 0;
        long ao;
        if (mode == 1) ao = (long)amc * (long)(A_ * NIN);
        else           ao = ((long)(amc / 19) * A_ + (amc % 19) + 1) * (long)NIN;
        aoff[j] = ao + kc * 8;
        boff[j] = (long)(col0 + r) * K + kc * 8;
    }

    const int arow = lane & 15;
    const int agrp = lane >> 4;
    const int brow = (lane & 7) + ((lane >> 4) << 3);
    const int bgrp = (lane >> 3) & 1;

    float d[4][8][4];
    #pragma unroll
    for (int mt = 0; mt < 4; mt++)
        #pragma unroll
        for (int nt = 0; nt < 8; nt++)
            #pragma unroll
            for (int q = 0; q < 4; q++) d[mt][nt][q] = 0.f;

    const int NK = K >> 6;

    #pragma unroll
    for (int s = 0; s < 2; s++) {
        const uint32_t so = s * STAGE_BYTES;
        const int koff = s * 64;
        #pragma unroll
        for (int j = 0; j < 8; j++) {
            cp_async16(dstA[j] + so, A + aoff[j] + koff, avalid[j]);
            cp_async16(dstB[j] + so, Bw + boff[j] + koff, 16);
        }
        asm volatile("cp.async.commit_group;" ::: "memory");
    }

    #pragma unroll 1
    for (int kb = 0; kb < NK; kb++) {
        asm volatile("cp.async.wait_group 1;" ::: "memory");
        __syncthreads();

        if (kb + 2 < NK) {
            const uint32_t so = ((kb + 2) % 3) * STAGE_BYTES;
            const int koff = (kb + 2) * 64;
            #pragma unroll
            for (int j = 0; j < 8; j++) {
                cp_async16(dstA[j] + so, A + aoff[j] + koff, avalid[j]);
                cp_async16(dstB[j] + so, Bw + boff[j] + koff, 16);
            }
        }
        asm volatile("cp.async.commit_group;" ::: "memory");

        const uint32_t sa  = sb + STG_A + (kb % 3) * STAGE_BYTES;
        const uint32_t sbs = sb + STG_B + (kb % 3) * STAGE_BYTES;
        #pragma unroll
        for (int kk = 0; kk < 4; kk++) {
            uint32_t afr[4][4];
            #pragma unroll
            for (int mt = 0; mt < 4; mt++) {
                const int r = wm + mt * 16 + arow;
                ldsm_x4(afr[mt], sa + r * 128 + (((2 * kk + agrp) ^ (r & 7)) * 16));
            }
            uint32_t bfr[4][4];
            #pragma unroll
            for (int nt2 = 0; nt2 < 4; nt2++) {
                const int r = wn + nt2 * 16 + brow;
                ldsm_x4(bfr[nt2], sbs + r * 128 + (((2 * kk + bgrp) ^ (r & 7)) * 16));
            }
            #pragma unroll
            for (int mt = 0; mt < 4; mt++)
                #pragma unroll
                for (int nt = 0; nt < 8; nt++)
                    mma_f16(d[mt][nt], afr[mt],
                            bfr[nt >> 1][(nt & 1) * 2], bfr[nt >> 1][(nt & 1) * 2 + 1]);
        }
    }

    float* __restrict__ C = g.C;
    const float* __restrict__ bias = g.bias;
    #pragma unroll
    for (int mt = 0; mt < 4; mt++) {
        const int rlo = row0 + wm + mt * 16 + (lane >> 2);
        const int rhi = rlo + 8;
        #pragma unroll
        for (int nt = 0; nt < 8; nt++) {
            const int col = col0 + wn + nt * 8 + (lane & 3) * 2;
            const float2 bv = *(const float2*)(bias + col);
            if (rlo < M) {
                float2 v; v.x = d[mt][nt][0] + bv.x; v.y = d[mt][nt][1] + bv.y;
                *(float2*)(C + (long)rlo * N + col) = v;
            }
            if (rhi < M) {
                float2 v; v.x = d[mt][nt][2] + bv.x; v.y = d[mt][nt][3] + bv.y;
                *(float2*)(C + (long)rhi * N + col) = v;
            }
        }
    }
}

__global__ __launch_bounds__(128, 2)
void fused_gemm(const GemmDesc d0, const GemmDesc d1, int split)
{
    extern __shared__ char smem[];
    const uint32_t sb = smem_u32(smem);
    const int i = blockIdx.x;
    if (i < split) gemm_core(d0, i, sb);
    else           gemm_core(d1, i - split, sb);
}

// ---------------------------------------------------------------------------
// Fused phys kernel v2 — COLUMN-SPLIT for 2 CTAs/SM.
// Grid = 2*1485. CTA = 128 threads (4 warps, 64x64 tiles).
//   cidx = blockIdx.x; pidx = cidx>>1 (pair row-block); half = cidx&1 (N half)
//   phase 1 (both halves duplicate): feat(128x32) @ Wp^T (+bp, relu) -> h1
//            full 128x256 fp16 in SMEM, computed as 2 sequential 128x128 passes
//   phase 2: h1 @ W3[col0:col0+128]^T (+b3) -> phys[:, col0:col0+128]
// SMEM: h1 64KB + union{feat 16K + Wp 32K | W3 2x16K} = 112KB -> 2 CTA/SM.
// Regs ~230*128 = 29K/CTA -> 2 CTAs fit the register file.
// ---------------------------------------------------------------------------
#define PH_H1   0                       // 128 rows x 512B (full h1)
#define PH_UN   65536
#define PH_FEAT (PH_UN)                 // 128 x 128B = 16KB
#define PH_WP   (PH_UN + 16384)         // 256 x 128B = 32KB
#define PH_SMEM (PH_UN + 49152)         // 114688 (112KB)

__global__ __launch_bounds__(128, 2)
void fused_phys2(const float* __restrict__ wcf,  // (BT, 20, 13) fp32
                 const float* __restrict__ Wp,   // (256, 26) fp32
                 const float* __restrict__ bp,   // (256)
                 const __half* __restrict__ W3h, // (256, 256) fp16
                 const float* __restrict__ b3,   // (256)
                 __half* __restrict__ phys)      // (MPAIR, 256) fp16
{
    extern __shared__ char smem[];
    const uint32_t sb = smem_u32(smem);
    const int tid  = threadIdx.x;
    const int wid  = tid >> 5;
    const int lane = tid & 31;
    const int pidx = blockIdx.x >> 1;
    const int half = blockIdx.x & 1;
    const int row0 = pidx * 128;
    const int col0 = half * 128;
    const int wm = (wid & 1) * 64;
    const int wn = (wid >> 1) * 64;

    // ---- fill feat (128 x 32 halves; zeros for k>=26 / invalid rows) ----
    #pragma unroll
    for (int j = 0; j < 32; j++) {
        const int e = tid + j * 128;   // 0..4095
        const int r = e >> 5, k = e & 31;
        const int row = row0 + r;
        float v = 0.f;
        if (k < 26 && row < MPAIR) {
            const int bt = row / NPAIR;
            const int p  = row % NPAIR;
            int i2 = 0, rem = p;
            while (rem >= 19 - i2) { rem -= 19 - i2; i2++; }
            const int j2 = i2 + 1 + rem;
            const int ag = (k < 13) ? i2 : j2;
            const int kk2 = (k < 13) ? k : k - 13;
            v = wcf[(long)bt * (A_ * 13) + ag * 13 + kk2];
        }
        const __half h = __float2half_rn(v);
        const unsigned short hs = *(const unsigned short*)&h;
        const uint32_t addr = sb + PH_FEAT + r * 128
                            + (((k >> 3) ^ (r & 7)) * 16) + (k & 7) * 2;
        asm volatile("st.shared.u16 [%0], %1;" :: "r"(addr), "h"(hs));
    }
    // ---- fill Wp (256 x 32 halves) ----
    #pragma unroll
    for (int j = 0; j < 64; j++) {
        const int e = tid + j * 128;   // 0..8191
        const int n = e >> 5, k = e & 31;
        const float v = (k < 26) ? Wp[n * 26 + k] : 0.f;
        const __half h = __float2half_rn(v);
        const unsigned short hs = *(const unsigned short*)&h;
        const uint32_t addr = sb + PH_WP + n * 128
                            + (((k >> 3) ^ (n & 7)) * 16) + (k & 7) * 2;
        asm volatile("st.shared.u16 [%0], %1;" :: "r"(addr), "h"(hs));
    }
    __syncthreads();

    const int arow = lane & 15;
    const int agrp = lane >> 4;
    const int brow = (lane & 7) + ((lane >> 4) << 3);
    const int bgrp = (lane >> 3) & 1;

    float d[4][8][4];

    // ---- phase 1: two sequential 128x128 passes -> full h1 in SMEM ----
    #pragma unroll 1
    for (int pn = 0; pn < 2; pn++) {
        #pragma unroll
        for (int mt = 0; mt < 4; mt++)
            #pragma unroll
            for (int nt = 0; nt < 8; nt++)
                #pragma unroll
                for (int q = 0; q < 4; q++) d[mt][nt][q] = 0.f;

        #pragma unroll
        for (int kk = 0; kk < 2; kk++) {
            uint32_t afr[4][4];
            #pragma unroll
            for (int mt = 0; mt < 4; mt++) {
                const int r = wm + mt * 16 + arow;
                ldsm_x4(afr[mt], sb + PH_FEAT + r * 128
                                 + (((2 * kk + agrp) ^ (r & 7)) * 16));
            }
            uint32_t bfr[4][4];
            #pragma unroll
            for (int nt2 = 0; nt2 < 4; nt2++) {
                const int r = pn * 128 + wn + nt2 * 16 + brow;
                ldsm_x4(bfr[nt2], sb + PH_WP + r * 128
                                  + (((2 * kk + bgrp) ^ (r & 7)) * 16));
            }
            #pragma unroll
            for (int mt = 0; mt < 4; mt++)
                #pragma unroll
                for (int nt = 0; nt < 8; nt++)
                    mma_f16(d[mt][nt], afr[mt],
                            bfr[nt >> 1][(nt & 1) * 2], bfr[nt >> 1][(nt & 1) * 2 + 1]);
        }

        // bias + relu -> h1 fp16 (512B pitch, 16B XOR swizzle)
        #pragma unroll
        for (int mt = 0; mt < 4; mt++) {
            const int rlo = wm + mt * 16 + (lane >> 2);
            const int rhi = rlo + 8;
            #pragma unroll
            for (int nt = 0; nt < 8; nt++) {
                const int c = pn * 128 + wn + nt * 8 + (lane & 3) * 2;
                const float2 bv = *(const float2*)(bp + c);
                const uint32_t blk = (uint32_t)(c >> 6) * 128 + (c & 7) * 2;
                const uint32_t kc = (uint32_t)((c & 63) >> 3);
                {
                    const __half2 h = __floats2half2_rn(fmaxf(d[mt][nt][0] + bv.x, 0.f),
                                                        fmaxf(d[mt][nt][1] + bv.y, 0.f));
                    const uint32_t u = *(const uint32_t*)&h;
                    asm volatile("st.shared.u32 [%0], %1;"
                        :: "r"(sb + PH_H1 + rlo * 512 + blk + ((kc ^ (rlo & 7)) * 16)),
                           "r"(u));
                }
                {
                    const __half2 h = __floats2half2_rn(fmaxf(d[mt][nt][2] + bv.x, 0.f),
                                                        fmaxf(d[mt][nt][3] + bv.y, 0.f));
                    const uint32_t u = *(const uint32_t*)&h;
                    asm volatile("st.shared.u32 [%0], %1;"
                        :: "r"(sb + PH_H1 + rhi * 512 + blk + ((kc ^ (rhi & 7)) * 16)),
                           "r"(u));
                }
            }
        }
    }
    __syncthreads();   // h1 complete; feat/Wp dead -> union reused for W3

    // ---- phase 2: this CTA's 128-wide W3 half, streamed in 4 k-chunks ----
    // W3 stage: 128 rows x 128B = 16KB; 2-stage ping-pong.
    #pragma unroll
    for (int s = 0; s < 2; s++) {
        const uint32_t so = sb + PH_UN + s * 16384;
        #pragma unroll
        for (int j = 0; j < 8; j++) {
            const int e = tid + j * 128;   // 0..1023
            const int n = e >> 3, kc = e & 7;
            cp_async16(so + n * 128 + ((kc ^ (n & 7)) * 16),
                       W3h + (long)(col0 + n) * 256 + s * 64 + kc * 8, 16);
        }
        asm volatile("cp.async.commit_group;" ::: "memory");
    }

    #pragma unroll
    for (int mt = 0; mt < 4; mt++)
        #pragma unroll
        for (int nt = 0; nt < 8; nt++)
            #pragma unroll
            for (int q = 0; q < 4; q++) d[mt][nt][q] = 0.f;

    #pragma unroll 1
    for (int kb = 0; kb < 4; kb++) {
        asm volatile("cp.async.wait_group 1;" ::: "memory");
        __syncthreads();

        const uint32_t sbs = sb + PH_UN + (kb & 1) * 16384;
        #pragma unroll
        for (int kk = 0; kk < 4; kk++) {
            uint32_t afr[4][4];
            #pragma unroll
            for (int mt = 0; mt < 4; mt++) {
                const int r = wm + mt * 16 + arow;
                ldsm_x4(afr[mt], sb + PH_H1 + r * 512 + kb * 128
                                 + (((2 * kk + agrp) ^ (r & 7)) * 16));
            }
            uint32_t bfr[4][4];
            #pragma unroll
            for (int nt2 = 0; nt2 < 4; nt2++) {
                const int r = wn + nt2 * 16 + brow;
                ldsm_x4(bfr[nt2], sbs + r * 128 + (((2 * kk + bgrp) ^ (r & 7)) * 16));
            }
            #pragma unroll
            for (int mt = 0; mt < 4; mt++)
                #pragma unroll
                for (int nt = 0; nt < 8; nt++)
                    mma_f16(d[mt][nt], afr[mt],
                            bfr[nt >> 1][(nt & 1) * 2], bfr[nt >> 1][(nt & 1) * 2 + 1]);
        }
        __syncthreads();   // stage consumed before refill

        if (kb + 2 < 4) {
            const uint32_t so = sb + PH_UN + (kb & 1) * 16384;
            #pragma unroll
            for (int j = 0; j < 8; j++) {
                const int e = tid + j * 128;
                const int n = e >> 3, kc = e & 7;
                cp_async16(so + n * 128 + ((kc ^ (n & 7)) * 16),
                           W3h + (long)(col0 + n) * 256 + (kb + 2) * 64 + kc * 8, 16);
            }
        }
        asm volatile("cp.async.commit_group;" ::: "memory");
    }

    // ---- epilogue: + b3, fp16 store of this CTA's N half ----
    #pragma unroll
    for (int mt = 0; mt < 4; mt++) {
        const int rlo = row0 + wm + mt * 16 + (lane >> 2);
        const int rhi = rlo + 8;
        #pragma unroll
        for (int nt = 0; nt < 8; nt++) {
            const int col = col0 + wn + nt * 8 + (lane & 3) * 2;
            const float2 bv = *(const float2*)(b3 + col);
            if (rlo < MPAIR) {
                const __half2 h = __floats2half2_rn(d[mt][nt][0] + bv.x,
                                                    d[mt][nt][1] + bv.y);
                *(__half2*)(phys + (long)rlo * NPHYS + col) = h;
            }
            if (rhi < MPAIR) {
                const __half2 h = __floats2half2_rn(d[mt][nt][2] + bv.x,
                                                    d[mt][nt][3] + bv.y);
                *(__half2*)(phys + (long)rhi * NPHYS + col) = h;
            }
        }
    }
}

// ---------------------------------------------------------------------------
// segmax: one CTA per bt, fp16 phys staged in smem (97KB), fp32 out, 2 CTA/SM.
// ---------------------------------------------------------------------------
#define SEG_SMEM (NPAIR * NPHYS * 2)   // 97280

__global__ __launch_bounds__(512, 2)
void segmax_smem(const __half* __restrict__ phys,  // (MPAIR, 256) fp16
                 float* __restrict__ out)          // (BT, 20, 256) fp32
{
    extern __shared__ __half tile[];   // [190][256] fp16
    const int bt  = blockIdx.x;
    const int tid = threadIdx.x;
    const uint4* src = (const uint4*)(phys + (long)bt * NPAIR * NPHYS);

    const int n16 = NPAIR * NPHYS * 2 / 16;   // 6080 uint4s
    #pragma unroll
    for (int i = 0; i < 12; i++) {
        const int e = tid + i * 512;
        if (e < n16) ((uint4*)tile)[e] = src[e];
    }
    __syncthreads();

    #pragma unroll
    for (int i = 0; i < 10; i++) {
        const int o = tid + i * 512;
        const int k = o >> 8, n = o & 255;
        float m = -CUDART_INF_F;
        #pragma unroll
        for (int other = 0; other < A_; other++) {
            if (other == k) continue;
            const int lo = (other < k) ? other : k;
            const int hi = (other < k) ? k : other;
            const int p = lo * 19 - (lo * (lo - 1)) / 2 + (hi - lo - 1);
            m = fmaxf(m, __half2float(tile[p * NPHYS + n]));
        }
        out[((long)bt * A_ + k) * NPHYS + n] = m;
    }
}

// ---------------------------------------------------------------------------
// Stream/event setup at static-init time (pre-checkpoint), with warm-up so no
// lazy driver allocations happen inside kernel_launch. Fixed fork-join pattern
// every call (graph-capturable; DisableTiming events).
// ---------------------------------------------------------------------------
struct StreamCtx {
    cudaStream_t s2;
    cudaEvent_t  e0, e1, e2, e3;
    StreamCtx() {
        cudaStreamCreateWithFlags(&s2, cudaStreamNonBlocking);
        cudaEventCreateWithFlags(&e0, cudaEventDisableTiming);
        cudaEventCreateWithFlags(&e1, cudaEventDisableTiming);
        cudaEventCreateWithFlags(&e2, cudaEventDisableTiming);
        cudaEventCreateWithFlags(&e3, cudaEventDisableTiming);
        warm_kernel<<<1, 32>>>();
        cudaEventRecord(e0, 0);
        cudaStreamWaitEvent(s2, e0, 0);
        warm_kernel<<<1, 32, 0, s2>>>();
        cudaEventRecord(e2, s2);
        cudaStreamWaitEvent(0, e2, 0);
        cudaDeviceSynchronize();
    }
};
static StreamCtx g_ctx;

// ---------------------------------------------------------------------------
extern "C" void kernel_launch(void* const* d_in, const int* in_sizes, int n_in,
                              void* d_out, int out_size)
{
    const float* x    = (const float*)d_in[0];
    const float* wcf  = (const float*)d_in[1];
    const float* Wg   = (const float*)d_in[2];
    const float* bg   = (const float*)d_in[3];
    const float* Wl   = (const float*)d_in[4];
    const float* bl   = (const float*)d_in[5];
    const float* Wp   = (const float*)d_in[6];
    const float* bp   = (const float*)d_in[7];
    const float* W3   = (const float*)d_in[8];
    const float* b3   = (const float*)d_in[9];

    float* out      = (float*)d_out;
    float* out_glob = out;                               // (1000,1024)
    float* out_loc  = out + (size_t)BT * NIMG;           // (19000,512)
    float* out_agt  = out_loc + (size_t)BT * 19 * NATT;  // (20000,256)

    __half *xh, *wlh, *wgh, *w3h, *physh;
    cudaGetSymbolAddress((void**)&xh,    g_xh);
    cudaGetSymbolAddress((void**)&wlh,   g_wlh);
    cudaGetSymbolAddress((void**)&wgh,   g_wgh);
    cudaGetSymbolAddress((void**)&w3h,   g_w3h);
    cudaGetSymbolAddress((void**)&physh, g_physh);

    cudaFuncSetAttribute(fused_gemm,  cudaFuncAttributeMaxDynamicSharedMemorySize, SM_GEMM);
    cudaFuncSetAttribute(fused_phys2, cudaFuncAttributeMaxDynamicSharedMemorySize, PH_SMEM);
    cudaFuncSetAttribute(segmax_smem, cudaFuncAttributeMaxDynamicSharedMemorySize, SEG_SMEM);

    cudaStream_t s2 = g_ctx.s2;

    // fork: side stream converts x/Wl/Wg (DRAM-bound) ...
    cudaEventRecord(g_ctx.e0, 0);
    cudaStreamWaitEvent(s2, g_ctx.e0, 0);
    cvt_f2h<<<2048, 256, 0, s2>>>(x,  xh,  (BT * A_ * NIN) / 4);
    cvt_f2h<<<256, 256, 0, s2>>>(Wl, wlh, (NATT * NIN) / 4);
    cvt_f2h<<<256, 256, 0, s2>>>(Wg, wgh, (NIMG * NIN) / 4);
    cudaEventRecord(g_ctx.e2, s2);

    // ... while main stream runs the tensor-bound phys chain (2 CTAs/SM now).
    cvt_f2h<<<64, 256>>>(W3, w3h, (NPHYS * NPHYS) / 4);
    fused_phys2<<<2 * ((MPAIR + 127) / 128), 128, PH_SMEM>>>(wcf, Wp, bp, w3h, b3, physh);
    cudaEventRecord(g_ctx.e1, 0);

    // segmax (DRAM-bound, needs phys) overlaps the gemm on the side stream.
    cudaStreamWaitEvent(s2, g_ctx.e1, 0);
    segmax_smem<<<BT, 512, SEG_SMEM, s2>>>(physh, out_agt);
    cudaEventRecord(g_ctx.e3, s2);

    // gemm on main after the fp16 conversions land.
    cudaStreamWaitEvent(0, g_ctx.e2, 0);
    {
        GemmDesc dl = { xh, wlh, bl, out_loc, BT * 19, NATT, NIN, 2 };
        GemmDesc dg = { xh, wgh, bg, out_glob, BT, NIMG, NIN, 1 };
        const int nLoc  = (NATT / 128) * ((BT * 19 + 127) / 128);   // 596
        const int nGlob = (NIMG / 128) * ((BT + 127) / 128);        // 64
        fused_gemm<<<nLoc + nGlob, 128, SM_GEMM>>>(dl, dg, nLoc);
    }

    // join side stream back into the origin stream.
    cudaStreamWaitEvent(0, g_ctx.e3, 0);
}

// round 15
// speedup vs baseline: 1.0124x; 1.0124x over previous
#include <cuda_runtime.h>
#include <cuda_fp16.h>
#include <cstdint>
#include <math_constants.h>

// ---------------------------------------------------------------------------
// Problem constants
// ---------------------------------------------------------------------------
#define B_  10
#define T_  100
#define A_  20
#define NIN 4096
#define NIMG 1024
#define NATT 512
#define NPHYS 256
#define BT  (B_*T_)            // 1000
#define NPAIR 190
#define MPAIR (BT*NPAIR)       // 190000

// Scratch (allocation-free rule: __device__ globals)
__device__ __align__(256) __half g_xh [(size_t)BT * A_ * NIN];   // fp16 x
__device__ __align__(256) __half g_wlh[(size_t)NATT * NIN];      // fp16 W_loc
__device__ __align__(256) __half g_wgh[(size_t)NIMG * NIN];      // fp16 W_glob
__device__ __align__(256) __half g_w3h[NPHYS * NPHYS];           // fp16 W_phys3
__device__ __align__(256) __half g_physh[(size_t)MPAIR * NPHYS]; // fp16 phys

// ---------------------------------------------------------------------------
// PTX helpers (sm_80-class ISA — tcgen05 rejected by this toolchain)
// ---------------------------------------------------------------------------
__device__ __forceinline__ uint32_t smem_u32(const void* p) {
    uint32_t a;
    asm("{ .reg .u64 t; cvta.to.shared.u64 t, %1; cvt.u32.u64 %0, t; }"
        : "=r"(a) : "l"(p));
    return a;
}

__device__ __forceinline__ void ldsm_x4(uint32_t* r, uint32_t addr) {
    asm volatile("ldmatrix.sync.aligned.m8n8.x4.shared.b16 {%0,%1,%2,%3}, [%4];"
                 : "=r"(r[0]), "=r"(r[1]), "=r"(r[2]), "=r"(r[3]) : "r"(addr));
}

__device__ __forceinline__ void mma_f16(float* d, const uint32_t* a,
                                        uint32_t b0, uint32_t b1) {
    asm volatile(
        "mma.sync.aligned.m16n8k16.row.col.f32.f16.f16.f32 "
        "{%0,%1,%2,%3}, {%4,%5,%6,%7}, {%8,%9}, {%0,%1,%2,%3};"
        : "+f"(d[0]), "+f"(d[1]), "+f"(d[2]), "+f"(d[3])
        : "r"(a[0]), "r"(a[1]), "r"(a[2]), "r"(a[3]), "r"(b0), "r"(b1));
}

__device__ __forceinline__ void cp_async16(uint32_t dst, const void* src, int sz) {
    asm volatile("cp.async.cg.shared.global [%0], [%1], 16, %2;"
                 :: "r"(dst), "l"(src), "r"(sz));
}

// ---------------------------------------------------------------------------
// fp32 -> fp16 convert (grid-stride, float4 -> 2x half2)
// ---------------------------------------------------------------------------
__global__ void cvt_f2h(const float* __restrict__ src, __half* __restrict__ dst,
                        int n4)
{
    const int stride = gridDim.x * blockDim.x;
    for (int i = blockIdx.x * blockDim.x + threadIdx.x; i < n4; i += stride) {
        const float4 v = ((const float4*)src)[i];
        ((__half2*)dst)[2 * i + 0] = __floats2half2_rn(v.x, v.y);
        ((__half2*)dst)[2 * i + 1] = __floats2half2_rn(v.z, v.w);
    }
}

__global__ void warm_kernel() {}

// ---------------------------------------------------------------------------
// fp16 GEMM: C[M,N] = gatherA[M,K] @ Bw[N,K]^T + bias (fp32 out)
//   mode 1: A row r at r*(20*4096)                    (glob: x[:,:,0,:])
//   mode 2: A row r at ((r/19)*20 + r%19 + 1)*4096    (loc: x[:,:,1:,:])
// CTA 128x128, 128 threads (4 warps x 64x64), BK=64, 3-stage, 2 CTA/SM.
// (round-7/11 configuration — best measured)
// ---------------------------------------------------------------------------
#define STG_A 0
#define STG_B 16384
#define STAGE_BYTES 32768
#define SM_GEMM (3 * STAGE_BYTES)   // 98304

struct GemmDesc {
    const __half* A; const __half* Bw; const float* bias; float* C;
    int M, N, K, mode;
};

__device__ __forceinline__ void gemm_core(const GemmDesc g, int idx, uint32_t sb)
{
    const __half* __restrict__ A  = g.A;
    const __half* __restrict__ Bw = g.Bw;
    const int M = g.M, N = g.N, K = g.K, mode = g.mode;

    const int nx   = N >> 7;
    const int row0 = (idx / nx) * 128;
    const int col0 = (idx % nx) * 128;

    const int tid  = threadIdx.x;
    const int wid  = tid >> 5;
    const int lane = tid & 31;
    const int wm = (wid & 1) * 64;
    const int wn = (wid >> 1) * 64;

    long aoff[8]; int avalid[8]; uint32_t dstA[8];
    long boff[8]; uint32_t dstB[8];
    #pragma unroll
    for (int j = 0; j < 8; j++) {
        const int e = tid + j * 128;
        const int r = e >> 3, kc = e & 7;
        const uint32_t sw = (uint32_t)(r * 128 + ((kc ^ (r & 7)) * 16));
        dstA[j] = sb + STG_A + sw;
        dstB[j] = sb + STG_B + sw;
        const int am = row0 + r;
        avalid[j] = (am < M) ? 16 : 0;
        const int amc = (am < M) ? am : 0;
        long ao;
        if (mode == 1) ao = (long)amc * (long)(A_ * NIN);
        else           ao = ((long)(amc / 19) * A_ + (amc % 19) + 1) * (long)NIN;
        aoff[j] = ao + kc * 8;
        boff[j] = (long)(col0 + r) * K + kc * 8;
    }

    const int arow = lane & 15;
    const int agrp = lane >> 4;
    const int brow = (lane & 7) + ((lane >> 4) << 3);
    const int bgrp = (lane >> 3) & 1;

    float d[4][8][4];
    #pragma unroll
    for (int mt = 0; mt < 4; mt++)
        #pragma unroll
        for (int nt = 0; nt < 8; nt++)
            #pragma unroll
            for (int q = 0; q < 4; q++) d[mt][nt][q] = 0.f;

    const int NK = K >> 6;

    #pragma unroll
    for (int s = 0; s < 2; s++) {
        const uint32_t so = s * STAGE_BYTES;
        const int koff = s * 64;
        #pragma unroll
        for (int j = 0; j < 8; j++) {
            cp_async16(dstA[j] + so, A + aoff[j] + koff, avalid[j]);
            cp_async16(dstB[j] + so, Bw + boff[j] + koff, 16);
        }
        asm volatile("cp.async.commit_group;" ::: "memory");
    }

    #pragma unroll 1
    for (int kb = 0; kb < NK; kb++) {
        asm volatile("cp.async.wait_group 1;" ::: "memory");
        __syncthreads();

        if (kb + 2 < NK) {
            const uint32_t so = ((kb + 2) % 3) * STAGE_BYTES;
            const int koff = (kb + 2) * 64;
            #pragma unroll
            for (int j = 0; j < 8; j++) {
                cp_async16(dstA[j] + so, A + aoff[j] + koff, avalid[j]);
                cp_async16(dstB[j] + so, Bw + boff[j] + koff, 16);
            }
        }
        asm volatile("cp.async.commit_group;" ::: "memory");

        const uint32_t sa  = sb + STG_A + (kb % 3) * STAGE_BYTES;
        const uint32_t sbs = sb + STG_B + (kb % 3) * STAGE_BYTES;
        #pragma unroll
        for (int kk = 0; kk < 4; kk++) {
            uint32_t afr[4][4];
            #pragma unroll
            for (int mt = 0; mt < 4; mt++) {
                const int r = wm + mt * 16 + arow;
                ldsm_x4(afr[mt], sa + r * 128 + (((2 * kk + agrp) ^ (r & 7)) * 16));
            }
            uint32_t bfr[4][4];
            #pragma unroll
            for (int nt2 = 0; nt2 < 4; nt2++) {
                const int r = wn + nt2 * 16 + brow;
                ldsm_x4(bfr[nt2], sbs + r * 128 + (((2 * kk + bgrp) ^ (r & 7)) * 16));
            }
            #pragma unroll
            for (int mt = 0; mt < 4; mt++)
                #pragma unroll
                for (int nt = 0; nt < 8; nt++)
                    mma_f16(d[mt][nt], afr[mt],
                            bfr[nt >> 1][(nt & 1) * 2], bfr[nt >> 1][(nt & 1) * 2 + 1]);
        }
    }

    float* __restrict__ C = g.C;
    const float* __restrict__ bias = g.bias;
    #pragma unroll
    for (int mt = 0; mt < 4; mt++) {
        const int rlo = row0 + wm + mt * 16 + (lane >> 2);
        const int rhi = rlo + 8;
        #pragma unroll
        for (int nt = 0; nt < 8; nt++) {
            const int col = col0 + wn + nt * 8 + (lane & 3) * 2;
            const float2 bv = *(const float2*)(bias + col);
            if (rlo < M) {
                float2 v; v.x = d[mt][nt][0] + bv.x; v.y = d[mt][nt][1] + bv.y;
                *(float2*)(C + (long)rlo * N + col) = v;
            }
            if (rhi < M) {
                float2 v; v.x = d[mt][nt][2] + bv.x; v.y = d[mt][nt][3] + bv.y;
                *(float2*)(C + (long)rhi * N + col) = v;
            }
        }
    }
}

__global__ __launch_bounds__(128, 2)
void fused_gemm(const GemmDesc d0, const GemmDesc d1, int split)
{
    extern __shared__ char smem[];
    const uint32_t sb = smem_u32(smem);
    const int i = blockIdx.x;
    if (i < split) gemm_core(d0, i, sb);
    else           gemm_core(d1, i - split, sb);
}

// ---------------------------------------------------------------------------
// Fused phys kernel v2 — COLUMN-SPLIT, co-residable with gemm CTAs
// (29K regs + 112KB smem per CTA; gemm CTA is 29K + 96KB -> one of each/SM).
// Grid = 2*1485, 128 threads. See round-14 notes; standalone it is slower than
// round-7 phys, but here it runs concurrently with cvt+gemm on the other
// stream, where its duration is (mostly) off the critical path.
// ---------------------------------------------------------------------------
#define PH_H1   0                       // 128 rows x 512B (full h1)
#define PH_UN   65536
#define PH_FEAT (PH_UN)                 // 128 x 128B = 16KB
#define PH_WP   (PH_UN + 16384)         // 256 x 128B = 32KB
#define PH_SMEM (PH_UN + 49152)         // 114688 (112KB)

__global__ __launch_bounds__(128, 2)
void fused_phys2(const float* __restrict__ wcf,  // (BT, 20, 13) fp32
                 const float* __restrict__ Wp,   // (256, 26) fp32
                 const float* __restrict__ bp,   // (256)
                 const __half* __restrict__ W3h, // (256, 256) fp16
                 const float* __restrict__ b3,   // (256)
                 __half* __restrict__ phys)      // (MPAIR, 256) fp16
{
    extern __shared__ char smem[];
    const uint32_t sb = smem_u32(smem);
    const int tid  = threadIdx.x;
    const int wid  = tid >> 5;
    const int lane = tid & 31;
    const int pidx = blockIdx.x >> 1;
    const int half = blockIdx.x & 1;
    const int row0 = pidx * 128;
    const int col0 = half * 128;
    const int wm = (wid & 1) * 64;
    const int wn = (wid >> 1) * 64;

    #pragma unroll
    for (int j = 0; j < 32; j++) {
        const int e = tid + j * 128;
        const int r = e >> 5, k = e & 31;
        const int row = row0 + r;
        float v = 0.f;
        if (k < 26 && row < MPAIR) {
            const int bt = row / NPAIR;
            const int p  = row % NPAIR;
            int i2 = 0, rem = p;
            while (rem >= 19 - i2) { rem -= 19 - i2; i2++; }
            const int j2 = i2 + 1 + rem;
            const int ag = (k < 13) ? i2 : j2;
            const int kk2 = (k < 13) ? k : k - 13;
            v = wcf[(long)bt * (A_ * 13) + ag * 13 + kk2];
        }
        const __half h = __float2half_rn(v);
        const unsigned short hs = *(const unsigned short*)&h;
        const uint32_t addr = sb + PH_FEAT + r * 128
                            + (((k >> 3) ^ (r & 7)) * 16) + (k & 7) * 2;
        asm volatile("st.shared.u16 [%0], %1;" :: "r"(addr), "h"(hs));
    }
    #pragma unroll
    for (int j = 0; j < 64; j++) {
        const int e = tid + j * 128;
        const int n = e >> 5, k = e & 31;
        const float v = (k < 26) ? Wp[n * 26 + k] : 0.f;
        const __half h = __float2half_rn(v);
        const unsigned short hs = *(const unsigned short*)&h;
        const uint32_t addr = sb + PH_WP + n * 128
                            + (((k >> 3) ^ (n & 7)) * 16) + (k & 7) * 2;
        asm volatile("st.shared.u16 [%0], %1;" :: "r"(addr), "h"(hs));
    }
    __syncthreads();

    const int arow = lane & 15;
    const int agrp = lane >> 4;
    const int brow = (lane & 7) + ((lane >> 4) << 3);
    const int bgrp = (lane >> 3) & 1;

    float d[4][8][4];

    #pragma unroll 1
    for (int pn = 0; pn < 2; pn++) {
        #pragma unroll
        for (int mt = 0; mt < 4; mt++)
            #pragma unroll
            for (int nt = 0; nt < 8; nt++)
                #pragma unroll
                for (int q = 0; q < 4; q++) d[mt][nt][q] = 0.f;

        #pragma unroll
        for (int kk = 0; kk < 2; kk++) {
            uint32_t afr[4][4];
            #pragma unroll
            for (int mt = 0; mt < 4; mt++) {
                const int r = wm + mt * 16 + arow;
                ldsm_x4(afr[mt], sb + PH_FEAT + r * 128
                                 + (((2 * kk + agrp) ^ (r & 7)) * 16));
            }
            uint32_t bfr[4][4];
            #pragma unroll
            for (int nt2 = 0; nt2 < 4; nt2++) {
                const int r = pn * 128 + wn + nt2 * 16 + brow;
                ldsm_x4(bfr[nt2], sb + PH_WP + r * 128
                                  + (((2 * kk + bgrp) ^ (r & 7)) * 16));
            }
            #pragma unroll
            for (int mt = 0; mt < 4; mt++)
                #pragma unroll
                for (int nt = 0; nt < 8; nt++)
                    mma_f16(d[mt][nt], afr[mt],
                            bfr[nt >> 1][(nt & 1) * 2], bfr[nt >> 1][(nt & 1) * 2 + 1]);
        }

        #pragma unroll
        for (int mt = 0; mt < 4; mt++) {
            const int rlo = wm + mt * 16 + (lane >> 2);
            const int rhi = rlo + 8;
            #pragma unroll
            for (int nt = 0; nt < 8; nt++) {
                const int c = pn * 128 + wn + nt * 8 + (lane & 3) * 2;
                const float2 bv = *(const float2*)(bp + c);
                const uint32_t blk = (uint32_t)(c >> 6) * 128 + (c & 7) * 2;
                const uint32_t kc = (uint32_t)((c & 63) >> 3);
                {
                    const __half2 h = __floats2half2_rn(fmaxf(d[mt][nt][0] + bv.x, 0.f),
                                                        fmaxf(d[mt][nt][1] + bv.y, 0.f));
                    const uint32_t u = *(const uint32_t*)&h;
                    asm volatile("st.shared.u32 [%0], %1;"
                        :: "r"(sb + PH_H1 + rlo * 512 + blk + ((kc ^ (rlo & 7)) * 16)),
                           "r"(u));
                }
                {
                    const __half2 h = __floats2half2_rn(fmaxf(d[mt][nt][2] + bv.x, 0.f),
                                                        fmaxf(d[mt][nt][3] + bv.y, 0.f));
                    const uint32_t u = *(const uint32_t*)&h;
                    asm volatile("st.shared.u32 [%0], %1;"
                        :: "r"(sb + PH_H1 + rhi * 512 + blk + ((kc ^ (rhi & 7)) * 16)),
                           "r"(u));
                }
            }
        }
    }
    __syncthreads();

    #pragma unroll
    for (int s = 0; s < 2; s++) {
        const uint32_t so = sb + PH_UN + s * 16384;
        #pragma unroll
        for (int j = 0; j < 8; j++) {
            const int e = tid + j * 128;
            const int n = e >> 3, kc = e & 7;
            cp_async16(so + n * 128 + ((kc ^ (n & 7)) * 16),
                       W3h + (long)(col0 + n) * 256 + s * 64 + kc * 8, 16);
        }
        asm volatile("cp.async.commit_group;" ::: "memory");
    }

    #pragma unroll
    for (int mt = 0; mt < 4; mt++)
        #pragma unroll
        for (int nt = 0; nt < 8; nt++)
            #pragma unroll
            for (int q = 0; q < 4; q++) d[mt][nt][q] = 0.f;

    #pragma unroll 1
    for (int kb = 0; kb < 4; kb++) {
        asm volatile("cp.async.wait_group 1;" ::: "memory");
        __syncthreads();

        const uint32_t sbs = sb + PH_UN + (kb & 1) * 16384;
        #pragma unroll
        for (int kk = 0; kk < 4; kk++) {
            uint32_t afr[4][4];
            #pragma unroll
            for (int mt = 0; mt < 4; mt++) {
                const int r = wm + mt * 16 + arow;
                ldsm_x4(afr[mt], sb + PH_H1 + r * 512 + kb * 128
                                 + (((2 * kk + agrp) ^ (r & 7)) * 16));
            }
            uint32_t bfr[4][4];
            #pragma unroll
            for (int nt2 = 0; nt2 < 4; nt2++) {
                const int r = wn + nt2 * 16 + brow;
                ldsm_x4(bfr[nt2], sbs + r * 128 + (((2 * kk + bgrp) ^ (r & 7)) * 16));
            }
            #pragma unroll
            for (int mt = 0; mt < 4; mt++)
                #pragma unroll
                for (int nt = 0; nt < 8; nt++)
                    mma_f16(d[mt][nt], afr[mt],
                            bfr[nt >> 1][(nt & 1) * 2], bfr[nt >> 1][(nt & 1) * 2 + 1]);
        }
        __syncthreads();

        if (kb + 2 < 4) {
            const uint32_t so = sb + PH_UN + (kb & 1) * 16384;
            #pragma unroll
            for (int j = 0; j < 8; j++) {
                const int e = tid + j * 128;
                const int n = e >> 3, kc = e & 7;
                cp_async16(so + n * 128 + ((kc ^ (n & 7)) * 16),
                           W3h + (long)(col0 + n) * 256 + (kb + 2) * 64 + kc * 8, 16);
            }
        }
        asm volatile("cp.async.commit_group;" ::: "memory");
    }

    #pragma unroll
    for (int mt = 0; mt < 4; mt++) {
        const int rlo = row0 + wm + mt * 16 + (lane >> 2);
        const int rhi = rlo + 8;
        #pragma unroll
        for (int nt = 0; nt < 8; nt++) {
            const int col = col0 + wn + nt * 8 + (lane & 3) * 2;
            const float2 bv = *(const float2*)(b3 + col);
            if (rlo < MPAIR) {
                const __half2 h = __floats2half2_rn(d[mt][nt][0] + bv.x,
                                                    d[mt][nt][1] + bv.y);
                *(__half2*)(phys + (long)rlo * NPHYS + col) = h;
            }
            if (rhi < MPAIR) {
                const __half2 h = __floats2half2_rn(d[mt][nt][2] + bv.x,
                                                    d[mt][nt][3] + bv.y);
                *(__half2*)(phys + (long)rhi * NPHYS + col) = h;
            }
        }
    }
}

// ---------------------------------------------------------------------------
// segmax: one CTA per bt, fp16 phys staged in smem (97KB), fp32 out, 2 CTA/SM.
// ---------------------------------------------------------------------------
#define SEG_SMEM (NPAIR * NPHYS * 2)   // 97280

__global__ __launch_bounds__(512, 2)
void segmax_smem(const __half* __restrict__ phys,  // (MPAIR, 256) fp16
                 float* __restrict__ out)          // (BT, 20, 256) fp32
{
    extern __shared__ __half tile[];   // [190][256] fp16
    const int bt  = blockIdx.x;
    const int tid = threadIdx.x;
    const uint4* src = (const uint4*)(phys + (long)bt * NPAIR * NPHYS);

    const int n16 = NPAIR * NPHYS * 2 / 16;   // 6080 uint4s
    #pragma unroll
    for (int i = 0; i < 12; i++) {
        const int e = tid + i * 512;
        if (e < n16) ((uint4*)tile)[e] = src[e];
    }
    __syncthreads();

    #pragma unroll
    for (int i = 0; i < 10; i++) {
        const int o = tid + i * 512;
        const int k = o >> 8, n = o & 255;
        float m = -CUDART_INF_F;
        #pragma unroll
        for (int other = 0; other < A_; other++) {
            if (other == k) continue;
            const int lo = (other < k) ? other : k;
            const int hi = (other < k) ? k : other;
            const int p = lo * 19 - (lo * (lo - 1)) / 2 + (hi - lo - 1);
            m = fmaxf(m, __half2float(tile[p * NPHYS + n]));
        }
        out[((long)bt * A_ + k) * NPHYS + n] = m;
    }
}

// ---------------------------------------------------------------------------
// Stream/event setup at static-init time (pre-checkpoint), with warm-up so no
// lazy driver allocations happen inside kernel_launch. Fixed fork-join pattern
// every call (graph-capturable; DisableTiming events).
// ---------------------------------------------------------------------------
struct StreamCtx {
    cudaStream_t s2;
    cudaEvent_t  e0, e2;
    StreamCtx() {
        cudaStreamCreateWithFlags(&s2, cudaStreamNonBlocking);
        cudaEventCreateWithFlags(&e0, cudaEventDisableTiming);
        cudaEventCreateWithFlags(&e2, cudaEventDisableTiming);
        warm_kernel<<<1, 32>>>();
        cudaEventRecord(e0, 0);
        cudaStreamWaitEvent(s2, e0, 0);
        warm_kernel<<<1, 32, 0, s2>>>();
        cudaEventRecord(e2, s2);
        cudaStreamWaitEvent(0, e2, 0);
        cudaDeviceSynchronize();
    }
};
static StreamCtx g_ctx;

// ---------------------------------------------------------------------------
extern "C" void kernel_launch(void* const* d_in, const int* in_sizes, int n_in,
                              void* d_out, int out_size)
{
    const float* x    = (const float*)d_in[0];
    const float* wcf  = (const float*)d_in[1];
    const float* Wg   = (const float*)d_in[2];
    const float* bg   = (const float*)d_in[3];
    const float* Wl   = (const float*)d_in[4];
    const float* bl   = (const float*)d_in[5];
    const float* Wp   = (const float*)d_in[6];
    const float* bp   = (const float*)d_in[7];
    const float* W3   = (const float*)d_in[8];
    const float* b3   = (const float*)d_in[9];

    float* out      = (float*)d_out;
    float* out_glob = out;                               // (1000,1024)
    float* out_loc  = out + (size_t)BT * NIMG;           // (19000,512)
    float* out_agt  = out_loc + (size_t)BT * 19 * NATT;  // (20000,256)

    __half *xh, *wlh, *wgh, *w3h, *physh;
    cudaGetSymbolAddress((void**)&xh,    g_xh);
    cudaGetSymbolAddress((void**)&wlh,   g_wlh);
    cudaGetSymbolAddress((void**)&wgh,   g_wgh);
    cudaGetSymbolAddress((void**)&w3h,   g_w3h);
    cudaGetSymbolAddress((void**)&physh, g_physh);

    cudaFuncSetAttribute(fused_gemm,  cudaFuncAttributeMaxDynamicSharedMemorySize, SM_GEMM);
    cudaFuncSetAttribute(fused_phys2, cudaFuncAttributeMaxDynamicSharedMemorySize, PH_SMEM);
    cudaFuncSetAttribute(segmax_smem, cudaFuncAttributeMaxDynamicSharedMemorySize, SEG_SMEM);

    cudaStream_t s2 = g_ctx.s2;

    // fork: side stream = cvt (DRAM-bound) then gemm (tensor-bound).
    cudaEventRecord(g_ctx.e0, 0);
    cudaStreamWaitEvent(s2, g_ctx.e0, 0);
    cvt_f2h<<<2048, 256, 0, s2>>>(x,  xh,  (BT * A_ * NIN) / 4);
    cvt_f2h<<<256, 256, 0, s2>>>(Wl, wlh, (NATT * NIN) / 4);
    cvt_f2h<<<256, 256, 0, s2>>>(Wg, wgh, (NIMG * NIN) / 4);
    {
        GemmDesc dl = { xh, wlh, bl, out_loc, BT * 19, NATT, NIN, 2 };
        GemmDesc dg = { xh, wgh, bg, out_glob, BT, NIMG, NIN, 1 };
        const int nLoc  = (NATT / 128) * ((BT * 19 + 127) / 128);   // 596
        const int nGlob = (NIMG / 128) * ((BT + 127) / 128);        // 64
        fused_gemm<<<nLoc + nGlob, 128, SM_GEMM, s2>>>(dl, dg, nLoc);
    }
    cudaEventRecord(g_ctx.e2, s2);

    // main stream: W3 cvt -> co-residable phys chain -> segmax.
    // phys2 CTAs share SMs with gemm CTAs (29K+29K regs, 112K+96K smem fit).
    cvt_f2h<<<64, 256>>>(W3, w3h, (NPHYS * NPHYS) / 4);
    fused_phys2<<<2 * ((MPAIR + 127) / 128), 128, PH_SMEM>>>(wcf, Wp, bp, w3h, b3, physh);
    segmax_smem<<<BT, 512, SEG_SMEM>>>(physh, out_agt);

    // join: origin stream waits for the gemm.
    cudaStreamWaitEvent(0, g_ctx.e2, 0);
}

// round 16
// speedup vs baseline: 1.0834x; 1.0702x over previous
#include <cuda_runtime.h>
#include <cuda_fp16.h>
#include <cstdint>
#include <math_constants.h>

// ---------------------------------------------------------------------------
// Problem constants
// ---------------------------------------------------------------------------
#define B_  10
#define T_  100
#define A_  20
#define NIN 4096
#define NIMG 1024
#define NATT 512
#define NPHYS 256
#define BT  (B_*T_)            // 1000
#define NPAIR 190
#define MPAIR (BT*NPAIR)       // 190000

// Scratch (allocation-free rule: __device__ globals)
__device__ __align__(256) __half g_xh [(size_t)BT * A_ * NIN];   // fp16 x
__device__ __align__(256) __half g_wlh[(size_t)NATT * NIN];      // fp16 W_loc
__device__ __align__(256) __half g_wgh[(size_t)NIMG * NIN];      // fp16 W_glob
__device__ __align__(256) __half g_w3h[NPHYS * NPHYS];           // fp16 W_phys3
__device__ __align__(256) __half g_physh[(size_t)MPAIR * NPHYS]; // fp16 phys

// ---------------------------------------------------------------------------
// PTX helpers (sm_80-class ISA — tcgen05 rejected by this toolchain)
// ---------------------------------------------------------------------------
__device__ __forceinline__ uint32_t smem_u32(const void* p) {
    uint32_t a;
    asm("{ .reg .u64 t; cvta.to.shared.u64 t, %1; cvt.u32.u64 %0, t; }"
        : "=r"(a) : "l"(p));
    return a;
}

__device__ __forceinline__ void ldsm_x4(uint32_t* r, uint32_t addr) {
    asm volatile("ldmatrix.sync.aligned.m8n8.x4.shared.b16 {%0,%1,%2,%3}, [%4];"
                 : "=r"(r[0]), "=r"(r[1]), "=r"(r[2]), "=r"(r[3]) : "r"(addr));
}

__device__ __forceinline__ void mma_f16(float* d, const uint32_t* a,
                                        uint32_t b0, uint32_t b1) {
    asm volatile(
        "mma.sync.aligned.m16n8k16.row.col.f32.f16.f16.f32 "
        "{%0,%1,%2,%3}, {%4,%5,%6,%7}, {%8,%9}, {%0,%1,%2,%3};"
        : "+f"(d[0]), "+f"(d[1]), "+f"(d[2]), "+f"(d[3])
        : "r"(a[0]), "r"(a[1]), "r"(a[2]), "r"(a[3]), "r"(b0), "r"(b1));
}

__device__ __forceinline__ void cp_async16(uint32_t dst, const void* src, int sz) {
    asm volatile("cp.async.cg.shared.global [%0], [%1], 16, %2;"
                 :: "r"(dst), "l"(src), "r"(sz));
}

// ---------------------------------------------------------------------------
// fp32 -> fp16 convert (grid-stride, float4 -> 2x half2)
// ---------------------------------------------------------------------------
__global__ void cvt_f2h(const float* __restrict__ src, __half* __restrict__ dst,
                        int n4)
{
    const int stride = gridDim.x * blockDim.x;
    for (int i = blockIdx.x * blockDim.x + threadIdx.x; i < n4; i += stride) {
        const float4 v = ((const float4*)src)[i];
        ((__half2*)dst)[2 * i + 0] = __floats2half2_rn(v.x, v.y);
        ((__half2*)dst)[2 * i + 1] = __floats2half2_rn(v.z, v.w);
    }
}

__global__ void warm_kernel() {}

// ---------------------------------------------------------------------------
// fp16 GEMM: C[M,N] = gatherA[M,K] @ Bw[N,K]^T + bias (fp32 out)
//   mode 1: A row r at r*(20*4096)                    (glob: x[:,:,0,:])
//   mode 2: A row r at ((r/19)*20 + r%19 + 1)*4096    (loc: x[:,:,1:,:])
// CTA 128x128, 128 threads (4 warps x 64x64), BK=64, 3-stage, 2 CTA/SM.
// (round-7/11 configuration — best measured)
// ---------------------------------------------------------------------------
#define STG_A 0
#define STG_B 16384
#define STAGE_BYTES 32768
#define SM_GEMM (3 * STAGE_BYTES)   // 98304

struct GemmDesc {
    const __half* A; const __half* Bw; const float* bias; float* C;
    int M, N, K, mode;
};

__device__ __forceinline__ void gemm_core(const GemmDesc g, int idx, uint32_t sb)
{
    const __half* __restrict__ A  = g.A;
    const __half* __restrict__ Bw = g.Bw;
    const int M = g.M, N = g.N, K = g.K, mode = g.mode;

    const int nx   = N >> 7;
    const int row0 = (idx / nx) * 128;
    const int col0 = (idx % nx) * 128;

    const int tid  = threadIdx.x;
    const int wid  = tid >> 5;
    const int lane = tid & 31;
    const int wm = (wid & 1) * 64;
    const int wn = (wid >> 1) * 64;

    long aoff[8]; int avalid[8]; uint32_t dstA[8];
    long boff[8]; uint32_t dstB[8];
    #pragma unroll
    for (int j = 0; j < 8; j++) {
        const int e = tid + j * 128;
        const int r = e >> 3, kc = e & 7;
        const uint32_t sw = (uint32_t)(r * 128 + ((kc ^ (r & 7)) * 16));
        dstA[j] = sb + STG_A + sw;
        dstB[j] = sb + STG_B + sw;
        const int am = row0 + r;
        avalid[j] = (am < M) ? 16 : 0;
        const int amc = (am < M) ? am : 0;
        long ao;
        if (mode == 1) ao = (long)amc * (long)(A_ * NIN);
        else           ao = ((long)(amc / 19) * A_ + (amc % 19) + 1) * (long)NIN;
        aoff[j] = ao + kc * 8;
        boff[j] = (long)(col0 + r) * K + kc * 8;
    }

    const int arow = lane & 15;
    const int agrp = lane >> 4;
    const int brow = (lane & 7) + ((lane >> 4) << 3);
    const int bgrp = (lane >> 3) & 1;

    float d[4][8][4];
    #pragma unroll
    for (int mt = 0; mt < 4; mt++)
        #pragma unroll
        for (int nt = 0; nt < 8; nt++)
            #pragma unroll
            for (int q = 0; q < 4; q++) d[mt][nt][q] = 0.f;

    const int NK = K >> 6;

    #pragma unroll
    for (int s = 0; s < 2; s++) {
        const uint32_t so = s * STAGE_BYTES;
        const int koff = s * 64;
        #pragma unroll
        for (int j = 0; j < 8; j++) {
            cp_async16(dstA[j] + so, A + aoff[j] + koff, avalid[j]);
            cp_async16(dstB[j] + so, Bw + boff[j] + koff, 16);
        }
        asm volatile("cp.async.commit_group;" ::: "memory");
    }

    #pragma unroll 1
    for (int kb = 0; kb < NK; kb++) {
        asm volatile("cp.async.wait_group 1;" ::: "memory");
        __syncthreads();

        if (kb + 2 < NK) {
            const uint32_t so = ((kb + 2) % 3) * STAGE_BYTES;
            const int koff = (kb + 2) * 64;
            #pragma unroll
            for (int j = 0; j < 8; j++) {
                cp_async16(dstA[j] + so, A + aoff[j] + koff, avalid[j]);
                cp_async16(dstB[j] + so, Bw + boff[j] + koff, 16);
            }
        }
        asm volatile("cp.async.commit_group;" ::: "memory");

        const uint32_t sa  = sb + STG_A + (kb % 3) * STAGE_BYTES;
        const uint32_t sbs = sb + STG_B + (kb % 3) * STAGE_BYTES;
        #pragma unroll
        for (int kk = 0; kk < 4; kk++) {
            uint32_t afr[4][4];
            #pragma unroll
            for (int mt = 0; mt < 4; mt++) {
                const int r = wm + mt * 16 + arow;
                ldsm_x4(afr[mt], sa + r * 128 + (((2 * kk + agrp) ^ (r & 7)) * 16));
            }
            uint32_t bfr[4][4];
            #pragma unroll
            for (int nt2 = 0; nt2 < 4; nt2++) {
                const int r = wn + nt2 * 16 + brow;
                ldsm_x4(bfr[nt2], sbs + r * 128 + (((2 * kk + bgrp) ^ (r & 7)) * 16));
            }
            #pragma unroll
            for (int mt = 0; mt < 4; mt++)
                #pragma unroll
                for (int nt = 0; nt < 8; nt++)
                    mma_f16(d[mt][nt], afr[mt],
                            bfr[nt >> 1][(nt & 1) * 2], bfr[nt >> 1][(nt & 1) * 2 + 1]);
        }
    }

    float* __restrict__ C = g.C;
    const float* __restrict__ bias = g.bias;
    #pragma unroll
    for (int mt = 0; mt < 4; mt++) {
        const int rlo = row0 + wm + mt * 16 + (lane >> 2);
        const int rhi = rlo + 8;
        #pragma unroll
        for (int nt = 0; nt < 8; nt++) {
            const int col = col0 + wn + nt * 8 + (lane & 3) * 2;
            const float2 bv = *(const float2*)(bias + col);
            if (rlo < M) {
                float2 v; v.x = d[mt][nt][0] + bv.x; v.y = d[mt][nt][1] + bv.y;
                *(float2*)(C + (long)rlo * N + col) = v;
            }
            if (rhi < M) {
                float2 v; v.x = d[mt][nt][2] + bv.x; v.y = d[mt][nt][3] + bv.y;
                *(float2*)(C + (long)rhi * N + col) = v;
            }
        }
    }
}

__global__ __launch_bounds__(128, 2)
void fused_gemm(const GemmDesc d0, const GemmDesc d1, int split)
{
    extern __shared__ char smem[];
    const uint32_t sb = smem_u32(smem);
    const int i = blockIdx.x;
    if (i < split) gemm_core(d0, i, sb);
    else           gemm_core(d1, i - split, sb);
}

// ---------------------------------------------------------------------------
// Fused phys kernel v3 — barrier-free phase 2.
// 256 threads, 8 warps (2Mx4N, 64x64 tiles), 1 CTA/SM (208KB smem).
// W3 chunks 0-2 (96KB) are cp.async'd DURING phase 1; chunk 3 lands in the
// dead Wp region after the h1 barrier. Phase 2 then runs 16 k-steps of MMA
// with zero __syncthreads / zero cp waits.
// SMEM: h1 64K @0 | feat 16K @64K | Wp 32K @80K (-> W3 chunk3)
//       | W3 chunks 0-2 96K @112K  -> total 208K
// ---------------------------------------------------------------------------
#define PH_H1   0
#define PH_FEAT 65536
#define PH_WP   81920
#define PH_W3   114688
#define PH_SMEM 212992          // 208 KB

__global__ __launch_bounds__(256, 1)
void fused_phys3(const float* __restrict__ wcf,  // (BT, 20, 13) fp32
                 const float* __restrict__ Wp,   // (256, 26) fp32
                 const float* __restrict__ bp,   // (256)
                 const __half* __restrict__ W3h, // (256, 256) fp16
                 const float* __restrict__ b3,   // (256)
                 __half* __restrict__ phys)      // (MPAIR, 256) fp16
{
    extern __shared__ char smem[];
    const uint32_t sb = smem_u32(smem);
    const int tid  = threadIdx.x;
    const int wid  = tid >> 5;
    const int lane = tid & 31;
    const int row0 = blockIdx.x * 128;
    const int wm = (wid & 1) * 64;
    const int wn = (wid >> 1) * 64;

    // ---- issue W3 chunks 0-2 (96KB) immediately; they land during phase 1 ----
    #pragma unroll
    for (int c = 0; c < 3; c++) {
        const uint32_t so = sb + PH_W3 + c * 32768;
        #pragma unroll
        for (int j = 0; j < 8; j++) {
            const int e = tid + j * 256;   // 0..2047
            const int n = e >> 3, kc = e & 7;
            cp_async16(so + n * 128 + ((kc ^ (n & 7)) * 16),
                       W3h + (long)n * 256 + c * 64 + kc * 8, 16);
        }
    }
    asm volatile("cp.async.commit_group;" ::: "memory");

    // ---- fill feat (128 x 32 halves, zeros for k>=26 / invalid rows) ----
    #pragma unroll
    for (int j = 0; j < 16; j++) {
        const int e = tid + j * 256;
        const int r = e >> 5, k = e & 31;
        const int row = row0 + r;
        float v = 0.f;
        if (k < 26 && row < MPAIR) {
            const int bt = row / NPAIR;
            const int p  = row % NPAIR;
            int i2 = 0, rem = p;
            while (rem >= 19 - i2) { rem -= 19 - i2; i2++; }
            const int j2 = i2 + 1 + rem;
            const int ag = (k < 13) ? i2 : j2;
            const int kk2 = (k < 13) ? k : k - 13;
            v = wcf[(long)bt * (A_ * 13) + ag * 13 + kk2];
        }
        const __half h = __float2half_rn(v);
        const unsigned short hs = *(const unsigned short*)&h;
        const uint32_t addr = sb + PH_FEAT + r * 128
                            + (((k >> 3) ^ (r & 7)) * 16) + (k & 7) * 2;
        asm volatile("st.shared.u16 [%0], %1;" :: "r"(addr), "h"(hs));
    }
    // ---- fill Wp (256 x 32 halves) ----
    #pragma unroll
    for (int j = 0; j < 32; j++) {
        const int e = tid + j * 256;
        const int n = e >> 5, k = e & 31;
        const float v = (k < 26) ? Wp[n * 26 + k] : 0.f;
        const __half h = __float2half_rn(v);
        const unsigned short hs = *(const unsigned short*)&h;
        const uint32_t addr = sb + PH_WP + n * 128
                            + (((k >> 3) ^ (n & 7)) * 16) + (k & 7) * 2;
        asm volatile("st.shared.u16 [%0], %1;" :: "r"(addr), "h"(hs));
    }
    __syncthreads();

    const int arow = lane & 15;
    const int agrp = lane >> 4;
    const int brow = (lane & 7) + ((lane >> 4) << 3);
    const int bgrp = (lane >> 3) & 1;

    float d[4][8][4];
    #pragma unroll
    for (int mt = 0; mt < 4; mt++)
        #pragma unroll
        for (int nt = 0; nt < 8; nt++)
            #pragma unroll
            for (int q = 0; q < 4; q++) d[mt][nt][q] = 0.f;

    // ---- phase 1 mma: K=32 (2 x k16) ----
    #pragma unroll
    for (int kk = 0; kk < 2; kk++) {
        uint32_t afr[4][4];
        #pragma unroll
        for (int mt = 0; mt < 4; mt++) {
            const int r = wm + mt * 16 + arow;
            ldsm_x4(afr[mt], sb + PH_FEAT + r * 128 + (((2 * kk + agrp) ^ (r & 7)) * 16));
        }
        uint32_t bfr[4][4];
        #pragma unroll
        for (int nt2 = 0; nt2 < 4; nt2++) {
            const int r = wn + nt2 * 16 + brow;
            ldsm_x4(bfr[nt2], sb + PH_WP + r * 128 + (((2 * kk + bgrp) ^ (r & 7)) * 16));
        }
        #pragma unroll
        for (int mt = 0; mt < 4; mt++)
            #pragma unroll
            for (int nt = 0; nt < 8; nt++)
                mma_f16(d[mt][nt], afr[mt],
                        bfr[nt >> 1][(nt & 1) * 2], bfr[nt >> 1][(nt & 1) * 2 + 1]);
    }

    // ---- bias + relu -> h1 fp16 (512B pitch, 16B XOR swizzle) ----
    #pragma unroll
    for (int mt = 0; mt < 4; mt++) {
        const int rlo = wm + mt * 16 + (lane >> 2);
        const int rhi = rlo + 8;
        #pragma unroll
        for (int nt = 0; nt < 8; nt++) {
            const int c = wn + nt * 8 + (lane & 3) * 2;
            const float2 bv = *(const float2*)(bp + c);
            const uint32_t blk = (uint32_t)(c >> 6) * 128 + (c & 7) * 2;
            const uint32_t kc = (uint32_t)((c & 63) >> 3);
            {
                const __half2 h = __floats2half2_rn(fmaxf(d[mt][nt][0] + bv.x, 0.f),
                                                    fmaxf(d[mt][nt][1] + bv.y, 0.f));
                const uint32_t u = *(const uint32_t*)&h;
                asm volatile("st.shared.u32 [%0], %1;"
                    :: "r"(sb + PH_H1 + rlo * 512 + blk + ((kc ^ (rlo & 7)) * 16)), "r"(u));
            }
            {
                const __half2 h = __floats2half2_rn(fmaxf(d[mt][nt][2] + bv.x, 0.f),
                                                    fmaxf(d[mt][nt][3] + bv.y, 0.f));
                const uint32_t u = *(const uint32_t*)&h;
                asm volatile("st.shared.u32 [%0], %1;"
                    :: "r"(sb + PH_H1 + rhi * 512 + blk + ((kc ^ (rhi & 7)) * 16)), "r"(u));
            }
            #pragma unroll
            for (int q = 0; q < 4; q++) d[mt][nt][q] = 0.f;
        }
    }
    __syncthreads();   // h1 visible; Wp reads done -> Wp region free

    // ---- chunk 3 into the dead Wp region; then all of W3 is resident ----
    #pragma unroll
    for (int j = 0; j < 8; j++) {
        const int e = tid + j * 256;
        const int n = e >> 3, kc = e & 7;
        cp_async16(sb + PH_WP + n * 128 + ((kc ^ (n & 7)) * 16),
                   W3h + (long)n * 256 + 3 * 64 + kc * 8, 16);
    }
    asm volatile("cp.async.commit_group;" ::: "memory");
    asm volatile("cp.async.wait_group 0;" ::: "memory");
    __syncthreads();

    // ---- phase 2: 16 k-steps of pure MMA, ZERO barriers ----
    #pragma unroll
    for (int kb = 0; kb < 4; kb++) {
        const uint32_t sbs = (kb < 3) ? (sb + PH_W3 + kb * 32768) : (sb + PH_WP);
        #pragma unroll
        for (int kk = 0; kk < 4; kk++) {
            uint32_t afr[4][4];
            #pragma unroll
            for (int mt = 0; mt < 4; mt++) {
                const int r = wm + mt * 16 + arow;
                ldsm_x4(afr[mt], sb + PH_H1 + r * 512 + kb * 128
                                 + (((2 * kk + agrp) ^ (r & 7)) * 16));
            }
            uint32_t bfr[4][4];
            #pragma unroll
            for (int nt2 = 0; nt2 < 4; nt2++) {
                const int r = wn + nt2 * 16 + brow;
                ldsm_x4(bfr[nt2], sbs + r * 128 + (((2 * kk + bgrp) ^ (r & 7)) * 16));
            }
            #pragma unroll
            for (int mt = 0; mt < 4; mt++)
                #pragma unroll
                for (int nt = 0; nt < 8; nt++)
                    mma_f16(d[mt][nt], afr[mt],
                            bfr[nt >> 1][(nt & 1) * 2], bfr[nt >> 1][(nt & 1) * 2 + 1]);
        }
    }

    // ---- epilogue: + b3, convert to fp16, store phys ----
    #pragma unroll
    for (int mt = 0; mt < 4; mt++) {
        const int rlo = row0 + wm + mt * 16 + (lane >> 2);
        const int rhi = rlo + 8;
        #pragma unroll
        for (int nt = 0; nt < 8; nt++) {
            const int col = wn + nt * 8 + (lane & 3) * 2;
            const float2 bv = *(const float2*)(b3 + col);
            if (rlo < MPAIR) {
                const __half2 h = __floats2half2_rn(d[mt][nt][0] + bv.x,
                                                    d[mt][nt][1] + bv.y);
                *(__half2*)(phys + (long)rlo * NPHYS + col) = h;
            }
            if (rhi < MPAIR) {
                const __half2 h = __floats2half2_rn(d[mt][nt][2] + bv.x,
                                                    d[mt][nt][3] + bv.y);
                *(__half2*)(phys + (long)rhi * NPHYS + col) = h;
            }
        }
    }
}

// ---------------------------------------------------------------------------
// segmax: one CTA per bt, fp16 phys staged in smem (97KB), fp32 out, 2 CTA/SM.
// ---------------------------------------------------------------------------
#define SEG_SMEM (NPAIR * NPHYS * 2)   // 97280

__global__ __launch_bounds__(512, 2)
void segmax_smem(const __half* __restrict__ phys,  // (MPAIR, 256) fp16
                 float* __restrict__ out)          // (BT, 20, 256) fp32
{
    extern __shared__ __half tile[];   // [190][256] fp16
    const int bt  = blockIdx.x;
    const int tid = threadIdx.x;
    const uint4* src = (const uint4*)(phys + (long)bt * NPAIR * NPHYS);

    const int n16 = NPAIR * NPHYS * 2 / 16;   // 6080 uint4s
    #pragma unroll
    for (int i = 0; i < 12; i++) {
        const int e = tid + i * 512;
        if (e < n16) ((uint4*)tile)[e] = src[e];
    }
    __syncthreads();

    #pragma unroll
    for (int i = 0; i < 10; i++) {
        const int o = tid + i * 512;
        const int k = o >> 8, n = o & 255;
        float m = -CUDART_INF_F;
        #pragma unroll
        for (int other = 0; other < A_; other++) {
            if (other == k) continue;
            const int lo = (other < k) ? other : k;
            const int hi = (other < k) ? k : other;
            const int p = lo * 19 - (lo * (lo - 1)) / 2 + (hi - lo - 1);
            m = fmaxf(m, __half2float(tile[p * NPHYS + n]));
        }
        out[((long)bt * A_ + k) * NPHYS + n] = m;
    }
}

// ---------------------------------------------------------------------------
// Stream/event setup at static-init time (pre-checkpoint), with warm-up so no
// lazy driver allocations happen inside kernel_launch. Fixed fork-join pattern
// every call (graph-capturable; DisableTiming events).
// ---------------------------------------------------------------------------
struct StreamCtx {
    cudaStream_t s2;
    cudaEvent_t  e0, e1, e2, e3;
    StreamCtx() {
        cudaStreamCreateWithFlags(&s2, cudaStreamNonBlocking);
        cudaEventCreateWithFlags(&e0, cudaEventDisableTiming);
        cudaEventCreateWithFlags(&e1, cudaEventDisableTiming);
        cudaEventCreateWithFlags(&e2, cudaEventDisableTiming);
        cudaEventCreateWithFlags(&e3, cudaEventDisableTiming);
        warm_kernel<<<1, 32>>>();
        cudaEventRecord(e0, 0);
        cudaStreamWaitEvent(s2, e0, 0);
        warm_kernel<<<1, 32, 0, s2>>>();
        cudaEventRecord(e2, s2);
        cudaStreamWaitEvent(0, e2, 0);
        cudaDeviceSynchronize();
    }
};
static StreamCtx g_ctx;

// ---------------------------------------------------------------------------
extern "C" void kernel_launch(void* const* d_in, const int* in_sizes, int n_in,
                              void* d_out, int out_size)
{
    const float* x    = (const float*)d_in[0];
    const float* wcf  = (const float*)d_in[1];
    const float* Wg   = (const float*)d_in[2];
    const float* bg   = (const float*)d_in[3];
    const float* Wl   = (const float*)d_in[4];
    const float* bl   = (const float*)d_in[5];
    const float* Wp   = (const float*)d_in[6];
    const float* bp   = (const float*)d_in[7];
    const float* W3   = (const float*)d_in[8];
    const float* b3   = (const float*)d_in[9];

    float* out      = (float*)d_out;
    float* out_glob = out;                               // (1000,1024)
    float* out_loc  = out + (size_t)BT * NIMG;           // (19000,512)
    float* out_agt  = out_loc + (size_t)BT * 19 * NATT;  // (20000,256)

    __half *xh, *wlh, *wgh, *w3h, *physh;
    cudaGetSymbolAddress((void**)&xh,    g_xh);
    cudaGetSymbolAddress((void**)&wlh,   g_wlh);
    cudaGetSymbolAddress((void**)&wgh,   g_wgh);
    cudaGetSymbolAddress((void**)&w3h,   g_w3h);
    cudaGetSymbolAddress((void**)&physh, g_physh);

    cudaFuncSetAttribute(fused_gemm,  cudaFuncAttributeMaxDynamicSharedMemorySize, SM_GEMM);
    cudaFuncSetAttribute(fused_phys3, cudaFuncAttributeMaxDynamicSharedMemorySize, PH_SMEM);
    cudaFuncSetAttribute(segmax_smem, cudaFuncAttributeMaxDynamicSharedMemorySize, SEG_SMEM);

    cudaStream_t s2 = g_ctx.s2;

    // fork: side stream converts x/Wl/Wg (DRAM-bound) ...
    cudaEventRecord(g_ctx.e0, 0);
    cudaStreamWaitEvent(s2, g_ctx.e0, 0);
    cvt_f2h<<<2048, 256, 0, s2>>>(x,  xh,  (BT * A_ * NIN) / 4);
    cvt_f2h<<<256, 256, 0, s2>>>(Wl, wlh, (NATT * NIN) / 4);
    cvt_f2h<<<256, 256, 0, s2>>>(Wg, wgh, (NIMG * NIN) / 4);
    cudaEventRecord(g_ctx.e2, s2);

    // ... while main stream runs the tensor-bound phys chain (barrier-free v3).
    cvt_f2h<<<64, 256>>>(W3, w3h, (NPHYS * NPHYS) / 4);
    fused_phys3<<<(MPAIR + 127) / 128, 256, PH_SMEM>>>(wcf, Wp, bp, w3h, b3, physh);
    cudaEventRecord(g_ctx.e1, 0);

    // segmax (DRAM-bound, needs phys) overlaps the gemm on the side stream.
    cudaStreamWaitEvent(s2, g_ctx.e1, 0);
    segmax_smem<<<BT, 512, SEG_SMEM, s2>>>(physh, out_agt);
    cudaEventRecord(g_ctx.e3, s2);

    // gemm on main after the fp16 conversions land.
    cudaStreamWaitEvent(0, g_ctx.e2, 0);
    {
        GemmDesc dl = { xh, wlh, bl, out_loc, BT * 19, NATT, NIN, 2 };
        GemmDesc dg = { xh, wgh, bg, out_glob, BT, NIMG, NIN, 1 };
        const int nLoc  = (NATT / 128) * ((BT * 19 + 127) / 128);   // 596
        const int nGlob = (NIMG / 128) * ((BT + 127) / 128);        // 64
        fused_gemm<<<nLoc + nGlob, 128, SM_GEMM>>>(dl, dg, nLoc);
    }

    // join side stream back into the origin stream.
    cudaStreamWaitEvent(0, g_ctx.e3, 0);
}